// round 8
// baseline (speedup 1.0000x reference)
#include <cuda_runtime.h>
#include <cuda_fp16.h>
#include <cstdint>

// ---------------- problem constants ----------------
#define T_TOK 2048
#define H_DIM 2048
#define F_DIM 5632
#define E_NUM 8
#define K_TOP 2
#define F2    (2 * F_DIM)

// ---------------- tiling ----------------
#define BM 128
#define BK 64
#define PITCH 72
#define TILE_B (BM * PITCH * 2)
#define STAGE_B (2 * TILE_B)
#define NSTAGE 3
#define MAXROWS  5120
#define MAXTILES 40

// ---------------- device scratch ----------------
__device__ __half g_W1h[(size_t)E_NUM * F2 * H_DIM];
__device__ __half g_W2h[(size_t)E_NUM * H_DIM * F_DIM];
__device__ __half g_xg [(size_t)MAXROWS * H_DIM];
__device__ __half g_act[(size_t)MAXROWS * F_DIM];
__device__ int   g_tok[MAXROWS];
__device__ float g_wt [MAXROWS];
__device__ int   g_tile_expert[MAXTILES];

// ---------------- helpers ----------------
__device__ __forceinline__ uint32_t smem_u32(const void* p) {
    uint32_t a;
    asm("{ .reg .u64 t; cvta.to.shared.u64 t, %1; cvt.u32.u64 %0, t; }" : "=r"(a) : "l"(p));
    return a;
}
__device__ __forceinline__ void cpa16(uint32_t dst, const void* src) {
    asm volatile("cp.async.cg.shared.global [%0], [%1], 16;" :: "r"(dst), "l"(src));
}
#define CPA_COMMIT() asm volatile("cp.async.commit_group;" ::: "memory")
#define CPA_WAIT0()  asm volatile("cp.async.wait_group 0;" ::: "memory")
#define CPA_WAIT1()  asm volatile("cp.async.wait_group 1;" ::: "memory")

__device__ __forceinline__ void ldm4(uint32_t* r, uint32_t addr) {
    asm volatile("ldmatrix.sync.aligned.m8n8.x4.shared.b16 {%0,%1,%2,%3}, [%4];"
                 : "=r"(r[0]), "=r"(r[1]), "=r"(r[2]), "=r"(r[3]) : "r"(addr));
}
__device__ __forceinline__ void mma16816(float* d, const uint32_t* a, const uint32_t* b) {
    asm volatile(
        "mma.sync.aligned.m16n8k16.row.col.f32.f16.f16.f32 "
        "{%0,%1,%2,%3}, {%4,%5,%6,%7}, {%8,%9}, {%0,%1,%2,%3};\n"
        : "+f"(d[0]), "+f"(d[1]), "+f"(d[2]), "+f"(d[3])
        : "r"(a[0]), "r"(a[1]), "r"(a[2]), "r"(a[3]),
          "r"(b[0]), "r"(b[1]));
}
__device__ __forceinline__ uint32_t pack_h2(float a, float b) {
    __half2 h = __floats2half2_rn(a, b);
    return *(uint32_t*)&h;
}

// ---------------- routing (merged) ----------------
__global__ void k_zero(float* __restrict__ out) {
    int tid = blockIdx.x * blockDim.x + threadIdx.x;
    int nt  = gridDim.x * blockDim.x;
    for (int i = tid; i < T_TOK * H_DIM; i += nt) out[i] = 0.0f;
}
// single block: count -> aligned prefix -> tile map -> scatter
__global__ void k_route(const int* __restrict__ sel, const float* __restrict__ rw) {
    __shared__ int cnt[E_NUM];
    __shared__ int cur[E_NUM];
    const int tid = threadIdx.x;
    if (tid < E_NUM) cnt[tid] = 0;
    for (int i = tid; i < MAXROWS; i += blockDim.x) { g_tok[i] = -1; g_wt[i] = 0.0f; }
    __syncthreads();
    for (int i = tid; i < T_TOK * K_TOP; i += blockDim.x) atomicAdd(&cnt[sel[i]], 1);
    __syncthreads();
    if (tid == 0) {
        for (int t = 0; t < MAXTILES; ++t) g_tile_expert[t] = -1;
        int off = 0;
        for (int e = 0; e < E_NUM; ++e) {
            cur[e] = off;
            int tiles = (cnt[e] + BM - 1) / BM;
            for (int j = 0; j < tiles; ++j) g_tile_expert[off / BM + j] = e;
            off += tiles * BM;
        }
    }
    __syncthreads();
    for (int i = tid; i < T_TOK * K_TOP; i += blockDim.x) {
        int e = sel[i];
        int pos = atomicAdd(&cur[e], 1);
        g_tok[pos] = i / K_TOP;
        g_wt[pos]  = rw[i];
    }
}
__global__ void k_gather(const float* __restrict__ X) {
    const int row = blockIdx.x;
    if (g_tile_expert[row >> 7] < 0) return;
    const int tok = g_tok[row];
    uint2* dst = (uint2*)(g_xg + (size_t)row * H_DIM);
    if (tok >= 0) {
        const float4* src = (const float4*)(X + (size_t)tok * H_DIM);
        for (int i = threadIdx.x; i < H_DIM / 4; i += blockDim.x) {
            float4 v = src[i];
            dst[i] = make_uint2(pack_h2(v.x, v.y), pack_h2(v.z, v.w));
        }
    } else {
        for (int i = threadIdx.x; i < H_DIM / 4; i += blockDim.x)
            dst[i] = make_uint2(0u, 0u);
    }
}
__global__ void k_cvt(const float* __restrict__ src, __half* __restrict__ dst, size_t n4) {
    size_t i = (size_t)blockIdx.x * blockDim.x + threadIdx.x;
    size_t stride = (size_t)gridDim.x * blockDim.x;
    for (; i < n4; i += stride) {
        float4 v = ((const float4*)src)[i];
        ((uint2*)dst)[i] = make_uint2(pack_h2(v.x, v.y), pack_h2(v.z, v.w));
    }
}

// ---------------- fp16 tensor GEMM, 3-stage cp.async (R6-proven) ----------------
template <int MODE>
__global__ void __launch_bounds__(256, 2)
k_gemm(const __half* __restrict__ Wh, float* __restrict__ out, int elo, int ehi) {
    constexpr int KD = (MODE == 1) ? H_DIM : F_DIM;
    constexpr int NC = KD / BK;

    const int tile_n = blockIdx.x;
    const int tile_m = blockIdx.y;
    const int e = g_tile_expert[tile_m];
    if (e < elo || e >= ehi) return;

    extern __shared__ char smem[];
    const uint32_t sb = smem_u32(smem);

    const int tid  = threadIdx.x;
    const int lane = tid & 31;
    const int warp = tid >> 5;
    const int wm   = warp & 1;
    const int wn   = warp >> 1;

    const __half* Abase = ((MODE == 1) ? g_xg : g_act) + (size_t)tile_m * BM * KD;
    const __half* Asrc[4];
    const __half* Bsrc[4];
    uint32_t doff[4];
    {
        const __half* Bg;
        const __half* Bu = nullptr;
        if (MODE == 1) {
            Bg = Wh + (size_t)e * F2 * H_DIM + (size_t)tile_n * 64 * H_DIM;
            Bu = Bg + (size_t)F_DIM * H_DIM;
        } else {
            Bg = Wh + (size_t)e * H_DIM * F_DIM + (size_t)tile_n * BM * F_DIM;
        }
#pragma unroll
        for (int i = 0; i < 4; ++i) {
            const int idx = i * 256 + tid;
            const int row = idx >> 3;
            const int q   = idx & 7;
            Asrc[i] = Abase + (size_t)row * KD + q * 8;
            if (MODE == 1)
                Bsrc[i] = (row < 64 ? Bg + (size_t)row * KD : Bu + (size_t)(row - 64) * KD) + q * 8;
            else
                Bsrc[i] = Bg + (size_t)row * KD + q * 8;
            doff[i] = (uint32_t)(row * (PITCH * 2) + q * 16);
        }
    }

    float acc[4][4][4];
#pragma unroll
    for (int mt = 0; mt < 4; ++mt)
#pragma unroll
        for (int nt = 0; nt < 4; ++nt)
#pragma unroll
            for (int r = 0; r < 4; ++r) acc[mt][nt][r] = 0.0f;

    const uint32_t lmoff = (uint32_t)((wm * 64 + (lane & 7) + ((lane >> 3) & 1) * 8) * (PITCH * 2)
                                      + (lane >> 4) * 16);
    const uint32_t lbofr = (uint32_t)((wn * 32 + ((lane >> 4) & 1) * 8 + (lane & 7)) * (PITCH * 2)
                                      + ((lane >> 3) & 1) * 16);

#pragma unroll
    for (int i = 0; i < 4; ++i) {
        cpa16(sb + doff[i], Asrc[i]);
        cpa16(sb + TILE_B + doff[i], Bsrc[i]);
    }
    CPA_COMMIT();
#pragma unroll
    for (int i = 0; i < 4; ++i) {
        cpa16(sb + STAGE_B + doff[i], Asrc[i] + BK);
        cpa16(sb + STAGE_B + TILE_B + doff[i], Bsrc[i] + BK);
    }
    CPA_COMMIT();

    int stage = 0;
#pragma unroll 1
    for (int c = 0; c < NC; ++c) {
        if (c + 2 < NC) CPA_WAIT1(); else CPA_WAIT0();
        __syncthreads();

        if (c + 2 < NC) {
            int s2 = stage + 2; if (s2 >= NSTAGE) s2 -= NSTAGE;
            const uint32_t base = sb + s2 * STAGE_B;
            const int koff = (c + 2) * BK;
#pragma unroll
            for (int i = 0; i < 4; ++i) {
                cpa16(base + doff[i], Asrc[i] + koff);
                cpa16(base + TILE_B + doff[i], Bsrc[i] + koff);
            }
            CPA_COMMIT();
        }

        const uint32_t As = sb + stage * STAGE_B;
        const uint32_t Bs = As + TILE_B;
#pragma unroll
        for (int ks = 0; ks < 4; ++ks) {
            uint32_t a[4][4];
#pragma unroll
            for (int mt = 0; mt < 4; ++mt)
                ldm4(a[mt], As + lmoff + mt * 16 * (PITCH * 2) + ks * 32);
            uint32_t b[4][2];
#pragma unroll
            for (int ntp = 0; ntp < 2; ++ntp) {
                uint32_t r[4];
                ldm4(r, Bs + lbofr + ntp * 16 * (PITCH * 2) + ks * 32);
                b[2 * ntp][0] = r[0]; b[2 * ntp][1] = r[1];
                b[2 * ntp + 1][0] = r[2]; b[2 * ntp + 1][1] = r[3];
            }
#pragma unroll
            for (int mt = 0; mt < 4; ++mt)
#pragma unroll
                for (int nt = 0; nt < 4; ++nt)
                    mma16816(acc[mt][nt], a[mt], b[nt]);
        }
        if (++stage >= NSTAGE) stage = 0;
    }

    // ---------------- epilogue ----------------
    if (MODE == 1) {
        constexpr int XP = 65;
        float* xg = (float*)smem;
        __syncthreads();
        if (wn < 2) {
#pragma unroll
            for (int mt = 0; mt < 4; ++mt) {
                const int r0 = wm * 64 + mt * 16 + (lane >> 2);
#pragma unroll
                for (int nt = 0; nt < 4; ++nt) {
                    const int c0 = wn * 32 + nt * 8 + (lane & 3) * 2;
                    xg[r0 * XP + c0]           = acc[mt][nt][0];
                    xg[r0 * XP + c0 + 1]       = acc[mt][nt][1];
                    xg[(r0 + 8) * XP + c0]     = acc[mt][nt][2];
                    xg[(r0 + 8) * XP + c0 + 1] = acc[mt][nt][3];
                }
            }
        }
        __syncthreads();
        if (wn >= 2) {
#pragma unroll
            for (int mt = 0; mt < 4; ++mt) {
                const int rl = wm * 64 + mt * 16 + (lane >> 2);
                const int grow0 = tile_m * BM + rl;
#pragma unroll
                for (int nt = 0; nt < 4; ++nt) {
                    const int c0 = (wn - 2) * 32 + nt * 8 + (lane & 3) * 2;
                    float g0 = xg[rl * XP + c0];
                    float g1 = xg[rl * XP + c0 + 1];
                    float g2 = xg[(rl + 8) * XP + c0];
                    float g3 = xg[(rl + 8) * XP + c0 + 1];
                    float o0 = acc[mt][nt][0] * g0 / (1.0f + expf(-g0));
                    float o1 = acc[mt][nt][1] * g1 / (1.0f + expf(-g1));
                    float o2 = acc[mt][nt][2] * g2 / (1.0f + expf(-g2));
                    float o3 = acc[mt][nt][3] * g3 / (1.0f + expf(-g3));
                    *(uint32_t*)(g_act + (size_t)grow0 * F_DIM + tile_n * 64 + c0)       = pack_h2(o0, o1);
                    *(uint32_t*)(g_act + (size_t)(grow0 + 8) * F_DIM + tile_n * 64 + c0) = pack_h2(o2, o3);
                }
            }
        }
    } else {
#pragma unroll
        for (int mt = 0; mt < 4; ++mt) {
            const int r0 = tile_m * BM + wm * 64 + mt * 16 + (lane >> 2);
            const int t0 = g_tok[r0];
            const int t1 = g_tok[r0 + 8];
            const float w0 = g_wt[r0];
            const float w1 = g_wt[r0 + 8];
#pragma unroll
            for (int nt = 0; nt < 4; ++nt) {
                const int c0 = tile_n * BM + wn * 32 + nt * 8 + (lane & 3) * 2;
                if (t0 >= 0) {
                    atomicAdd(out + (size_t)t0 * H_DIM + c0,     w0 * acc[mt][nt][0]);
                    atomicAdd(out + (size_t)t0 * H_DIM + c0 + 1, w0 * acc[mt][nt][1]);
                }
                if (t1 >= 0) {
                    atomicAdd(out + (size_t)t1 * H_DIM + c0,     w1 * acc[mt][nt][2]);
                    atomicAdd(out + (size_t)t1 * H_DIM + c0 + 1, w1 * acc[mt][nt][3]);
                }
            }
        }
    }
}

// ---------------- launch ----------------
extern "C" void kernel_launch(void* const* d_in, const int* in_sizes, int n_in,
                              void* d_out, int out_size) {
    const float* X   = (const float*)d_in[0];
    const float* rw  = (const float*)d_in[1];
    const int*   sel = (const int*)  d_in[2];
    const float* W1  = (const float*)d_in[3];
    const float* W2  = (const float*)d_in[4];
    float* out = (float*)d_out;

    constexpr int SMEM = NSTAGE * STAGE_B;     // 110592
    constexpr int NSLICE = 4;                  // W1 cvt slices (2 experts each)

    static int cfg = 0;
    static __half* w1h = nullptr;
    static __half* w2h = nullptr;
    static cudaStream_t sCvt, sRoute;
    static cudaEvent_t evSlice[NSLICE], evW2, evRoute, evFork;
    if (!cfg) {
        cudaFuncSetAttribute(k_gemm<1>, cudaFuncAttributeMaxDynamicSharedMemorySize, SMEM);
        cudaFuncSetAttribute(k_gemm<2>, cudaFuncAttributeMaxDynamicSharedMemorySize, SMEM);
        cudaGetSymbolAddress((void**)&w1h, g_W1h);
        cudaGetSymbolAddress((void**)&w2h, g_W2h);
        cudaStreamCreate(&sCvt);
        cudaStreamCreate(&sRoute);
        for (int i = 0; i < NSLICE; ++i)
            cudaEventCreateWithFlags(&evSlice[i], cudaEventDisableTiming);
        cudaEventCreateWithFlags(&evW2,    cudaEventDisableTiming);
        cudaEventCreateWithFlags(&evRoute, cudaEventDisableTiming);
        cudaEventCreateWithFlags(&evFork,  cudaEventDisableTiming);
        cfg = 1;
    }

    const size_t W1_ELEMS = (size_t)E_NUM * F2 * H_DIM;
    const size_t SLICE    = W1_ELEMS / NSLICE;
    const size_t W2_ELEMS = (size_t)E_NUM * H_DIM * F_DIM;

    // fork both side streams off the default stream head
    cudaEventRecord(evFork, 0);
    cudaStreamWaitEvent(sRoute, evFork, 0);
    cudaStreamWaitEvent(sCvt,   evFork, 0);

    // routing stream
    k_zero<<<256, 256, 0, sRoute>>>(out);
    k_route<<<1, 1024, 0, sRoute>>>(sel, rw);
    k_gather<<<MAXROWS, 256, 0, sRoute>>>(X);
    cudaEventRecord(evRoute, sRoute);

    // cvt stream: W1 in expert-pair slices, then W2
    for (int i = 0; i < NSLICE; ++i) {
        k_cvt<<<1024, 256, 0, sCvt>>>(W1 + i * SLICE, w1h + i * SLICE, SLICE / 4);
        cudaEventRecord(evSlice[i], sCvt);
    }
    k_cvt<<<2048, 256, 0, sCvt>>>(W2, w2h, W2_ELEMS / 4);
    cudaEventRecord(evW2, sCvt);

    // main stream: GEMM1 per slice, then GEMM2
    cudaStreamWaitEvent(0, evRoute, 0);
    dim3 g1(F_DIM / 64, MAXTILES);
    for (int i = 0; i < NSLICE; ++i) {
        cudaStreamWaitEvent(0, evSlice[i], 0);
        k_gemm<1><<<g1, 256, SMEM>>>(w1h, nullptr, i * (E_NUM / NSLICE), (i + 1) * (E_NUM / NSLICE));
    }
    cudaStreamWaitEvent(0, evW2, 0);
    dim3 g2(H_DIM / BM, MAXTILES);
    k_gemm<2><<<g2, 256, SMEM>>>(w2h, out, 0, E_NUM);
}

// round 9
// speedup vs baseline: 1.2855x; 1.2855x over previous
#include <cuda_runtime.h>
#include <cuda_fp16.h>
#include <cstdint>

// ---------------- problem constants ----------------
#define T_TOK 2048
#define H_DIM 2048
#define F_DIM 5632
#define E_NUM 8
#define K_TOP 2
#define F2    (2 * F_DIM)

// ---------------- tiling ----------------
#define BM 128
#define BK 64
#define PITCH 72                    // A fp16 pitch in halves (144B)
#define PITCH32 68                  // B fp32 pitch in floats (272B)
#define A16_B (BM * PITCH * 2)      // 18432
#define B32_B (BM * PITCH32 * 4)    // 34816
#define STAGE_SZ (A16_B + B32_B)    // 53248
#define OFF_B32 A16_B
#define MAXROWS  5120
#define MAXTILES 40

// ---------------- device scratch ----------------
__device__ __half g_xg [(size_t)MAXROWS * H_DIM];
__device__ __half g_act[(size_t)MAXROWS * F_DIM];
__device__ int   g_tok[MAXROWS];
__device__ float g_wt [MAXROWS];
__device__ int   g_tile_expert[MAXTILES];

// ---------------- helpers ----------------
__device__ __forceinline__ uint32_t smem_u32(const void* p) {
    uint32_t a;
    asm("{ .reg .u64 t; cvta.to.shared.u64 t, %1; cvt.u32.u64 %0, t; }" : "=r"(a) : "l"(p));
    return a;
}
__device__ __forceinline__ void cpa16(uint32_t dst, const void* src) {
    asm volatile("cp.async.cg.shared.global [%0], [%1], 16;" :: "r"(dst), "l"(src));
}
#define CPA_COMMIT() asm volatile("cp.async.commit_group;" ::: "memory")
#define CPA_WAIT0()  asm volatile("cp.async.wait_group 0;" ::: "memory")

__device__ __forceinline__ void ldm4(uint32_t* r, uint32_t addr) {
    asm volatile("ldmatrix.sync.aligned.m8n8.x4.shared.b16 {%0,%1,%2,%3}, [%4];"
                 : "=r"(r[0]), "=r"(r[1]), "=r"(r[2]), "=r"(r[3]) : "r"(addr));
}
__device__ __forceinline__ void mma16816(float* d, const uint32_t* a, const uint32_t* b) {
    asm volatile(
        "mma.sync.aligned.m16n8k16.row.col.f32.f16.f16.f32 "
        "{%0,%1,%2,%3}, {%4,%5,%6,%7}, {%8,%9}, {%0,%1,%2,%3};\n"
        : "+f"(d[0]), "+f"(d[1]), "+f"(d[2]), "+f"(d[3])
        : "r"(a[0]), "r"(a[1]), "r"(a[2]), "r"(a[3]),
          "r"(b[0]), "r"(b[1]));
}
__device__ __forceinline__ uint32_t pack_h2(float a, float b) {
    __half2 h = __floats2half2_rn(a, b);
    return *(uint32_t*)&h;
}

// ---------------- routing ----------------
__global__ void k_zero(float* __restrict__ out) {
    int tid = blockIdx.x * blockDim.x + threadIdx.x;
    int nt  = gridDim.x * blockDim.x;
    for (int i = tid; i < T_TOK * H_DIM; i += nt) out[i] = 0.0f;
}
__global__ void k_route(const int* __restrict__ sel, const float* __restrict__ rw) {
    __shared__ int cnt[E_NUM];
    __shared__ int cur[E_NUM];
    const int tid = threadIdx.x;
    if (tid < E_NUM) cnt[tid] = 0;
    for (int i = tid; i < MAXROWS; i += blockDim.x) { g_tok[i] = -1; g_wt[i] = 0.0f; }
    __syncthreads();
    for (int i = tid; i < T_TOK * K_TOP; i += blockDim.x) atomicAdd(&cnt[sel[i]], 1);
    __syncthreads();
    if (tid == 0) {
        for (int t = 0; t < MAXTILES; ++t) g_tile_expert[t] = -1;
        int off = 0;
        for (int e = 0; e < E_NUM; ++e) {
            cur[e] = off;
            int tiles = (cnt[e] + BM - 1) / BM;
            for (int j = 0; j < tiles; ++j) g_tile_expert[off / BM + j] = e;
            off += tiles * BM;
        }
    }
    __syncthreads();
    for (int i = tid; i < T_TOK * K_TOP; i += blockDim.x) {
        int e = sel[i];
        int pos = atomicAdd(&cur[e], 1);
        g_tok[pos] = i / K_TOP;
        g_wt[pos]  = rw[i];
    }
}
__global__ void k_gather(const float* __restrict__ X) {
    const int row = blockIdx.x;
    if (g_tile_expert[row >> 7] < 0) return;
    const int tok = g_tok[row];
    uint2* dst = (uint2*)(g_xg + (size_t)row * H_DIM);
    if (tok >= 0) {
        const float4* src = (const float4*)(X + (size_t)tok * H_DIM);
        for (int i = threadIdx.x; i < H_DIM / 4; i += blockDim.x) {
            float4 v = src[i];
            dst[i] = make_uint2(pack_h2(v.x, v.y), pack_h2(v.z, v.w));
        }
    } else {
        for (int i = threadIdx.x; i < H_DIM / 4; i += blockDim.x)
            dst[i] = make_uint2(0u, 0u);
    }
}

// ---------------- fp16 tensor GEMM, fp32 B converted in registers ----------------
// grid: x = tile_m (fast -> B reused via L2 across same-expert M-tiles), y = tile_n
// MODE 1: A = g_xg [128 x H] fp16, B = 64 gate ‖ 64 up fp32 rows of W1[e] -> silu -> g_act
// MODE 2: A = g_act [128 x F] fp16, B = 128 fp32 rows of W2[e] -> weighted atomicAdd -> out
template <int MODE>
__global__ void __launch_bounds__(256, 2)
k_gemm(const float* __restrict__ W, float* __restrict__ out) {
    constexpr int KD = (MODE == 1) ? H_DIM : F_DIM;
    constexpr int NC = KD / BK;               // 32 or 88

    const int tile_m = blockIdx.x;
    const int tile_n = blockIdx.y;
    const int e = g_tile_expert[tile_m];
    if (e < 0) return;

    extern __shared__ char smem[];
    const uint32_t sb = smem_u32(smem);

    const int tid  = threadIdx.x;
    const int lane = tid & 31;
    const int warp = tid >> 5;
    const int wm   = warp & 1;
    const int wn   = warp >> 1;

    // A cp.async: 1024 granules, 4/thread; row = j*32 + (tid>>3), q = tid&7
    const __half* Aptr = (((MODE == 1) ? g_xg : g_act) + (size_t)tile_m * BM * KD)
                         + (size_t)(tid >> 3) * KD + (tid & 7) * 8;
    const uint32_t doffA = (uint32_t)((tid >> 3) * (PITCH * 2) + (tid & 7) * 16);

    // B fp32 cp.async: 2048 granules, 8/thread; row = j*16 + (tid>>4), q = tid&15
    const int brow = tid >> 4;                 // 0..15
    const int bq   = tid & 15;                 // float4 index in row
    const float* ptrG;
    const float* ptrU = nullptr;
    if (MODE == 1) {
        const float* Bg = W + (size_t)e * F2 * H_DIM + (size_t)tile_n * 64 * H_DIM;
        ptrG = Bg + (size_t)brow * KD + bq * 4;
        ptrU = Bg + (size_t)F_DIM * H_DIM + (size_t)brow * KD + bq * 4;
    } else {
        ptrG = (W + (size_t)e * H_DIM * F_DIM + (size_t)tile_n * BM * F_DIM)
               + (size_t)brow * KD + bq * 4;
    }
    const uint32_t doffB = (uint32_t)(brow * (PITCH32 * 4) + bq * 16);

    float acc[4][4][4];
#pragma unroll
    for (int mt = 0; mt < 4; ++mt)
#pragma unroll
        for (int nt = 0; nt < 4; ++nt)
#pragma unroll
            for (int r = 0; r < 4; ++r) acc[mt][nt][r] = 0.0f;

    // A ldmatrix lane base (within A16 tile)
    const uint32_t lmoff = (uint32_t)((wm * 64 + (lane & 7) + ((lane >> 3) & 1) * 8) * (PITCH * 2)
                                      + (lane >> 4) * 16);
    // B fragment base: row n = wn*32 + (lane>>2), k offset (lane&3)*2 floats
    const uint32_t lboff = (uint32_t)((wn * 32 + (lane >> 2)) * (PITCH32 * 4) + (lane & 3) * 8);

    auto issue = [&](int c, int s) {
        const uint32_t base = sb + s * STAGE_SZ;
        const int koff = c * BK;
#pragma unroll
        for (int j = 0; j < 4; ++j)
            cpa16(base + doffA + j * 32 * (PITCH * 2), Aptr + (size_t)j * 32 * KD + koff);
#pragma unroll
        for (int j = 0; j < 8; ++j) {
            const float* src = (MODE == 1)
                ? ((j < 4) ? ptrG + (size_t)j * 16 * KD : ptrU + (size_t)(j - 4) * 16 * KD)
                : ptrG + (size_t)j * 16 * KD;
            cpa16(base + OFF_B32 + doffB + j * 16 * (PITCH32 * 4), src + koff);
        }
        CPA_COMMIT();
    };

    issue(0, 0);

#pragma unroll 1
    for (int c = 0; c < NC; ++c) {
        const int s = c & 1;
        CPA_WAIT0();
        __syncthreads();
        if (c + 1 < NC) issue(c + 1, s ^ 1);

        const uint32_t As = sb + s * STAGE_SZ;
        const char* Bs = smem + s * STAGE_SZ + OFF_B32;
#pragma unroll
        for (int ks = 0; ks < 4; ++ks) {
            uint32_t a[4][4];
#pragma unroll
            for (int mt = 0; mt < 4; ++mt)
                ldm4(a[mt], As + lmoff + mt * 16 * (PITCH * 2) + ks * 32);
            uint32_t b[4][2];
#pragma unroll
            for (int nt = 0; nt < 4; ++nt) {
                const char* bp = Bs + lboff + nt * 8 * (PITCH32 * 4) + ks * 64;
                float2 v0 = *(const float2*)bp;
                float2 v1 = *(const float2*)(bp + 32);
                b[nt][0] = pack_h2(v0.x, v0.y);
                b[nt][1] = pack_h2(v1.x, v1.y);
            }
#pragma unroll
            for (int mt = 0; mt < 4; ++mt)
#pragma unroll
                for (int nt = 0; nt < 4; ++nt)
                    mma16816(acc[mt][nt], a[mt], b[nt]);
        }
    }

    // ---------------- epilogue ----------------
    if (MODE == 1) {
        constexpr int XP = 65;
        float* xg = (float*)smem;
        __syncthreads();
        if (wn < 2) {
#pragma unroll
            for (int mt = 0; mt < 4; ++mt) {
                const int r0 = wm * 64 + mt * 16 + (lane >> 2);
#pragma unroll
                for (int nt = 0; nt < 4; ++nt) {
                    const int c0 = wn * 32 + nt * 8 + (lane & 3) * 2;
                    xg[r0 * XP + c0]           = acc[mt][nt][0];
                    xg[r0 * XP + c0 + 1]       = acc[mt][nt][1];
                    xg[(r0 + 8) * XP + c0]     = acc[mt][nt][2];
                    xg[(r0 + 8) * XP + c0 + 1] = acc[mt][nt][3];
                }
            }
        }
        __syncthreads();
        if (wn >= 2) {
#pragma unroll
            for (int mt = 0; mt < 4; ++mt) {
                const int rl = wm * 64 + mt * 16 + (lane >> 2);
                const int grow0 = tile_m * BM + rl;
#pragma unroll
                for (int nt = 0; nt < 4; ++nt) {
                    const int c0 = (wn - 2) * 32 + nt * 8 + (lane & 3) * 2;
                    float g0 = xg[rl * XP + c0];
                    float g1 = xg[rl * XP + c0 + 1];
                    float g2 = xg[(rl + 8) * XP + c0];
                    float g3 = xg[(rl + 8) * XP + c0 + 1];
                    float o0 = acc[mt][nt][0] * g0 / (1.0f + expf(-g0));
                    float o1 = acc[mt][nt][1] * g1 / (1.0f + expf(-g1));
                    float o2 = acc[mt][nt][2] * g2 / (1.0f + expf(-g2));
                    float o3 = acc[mt][nt][3] * g3 / (1.0f + expf(-g3));
                    *(uint32_t*)(g_act + (size_t)grow0 * F_DIM + tile_n * 64 + c0)       = pack_h2(o0, o1);
                    *(uint32_t*)(g_act + (size_t)(grow0 + 8) * F_DIM + tile_n * 64 + c0) = pack_h2(o2, o3);
                }
            }
        }
    } else {
#pragma unroll
        for (int mt = 0; mt < 4; ++mt) {
            const int r0 = tile_m * BM + wm * 64 + mt * 16 + (lane >> 2);
            const int t0 = g_tok[r0];
            const int t1 = g_tok[r0 + 8];
            const float w0 = g_wt[r0];
            const float w1 = g_wt[r0 + 8];
#pragma unroll
            for (int nt = 0; nt < 4; ++nt) {
                const int c0 = tile_n * BM + wn * 32 + nt * 8 + (lane & 3) * 2;
                if (t0 >= 0) {
                    atomicAdd(out + (size_t)t0 * H_DIM + c0,     w0 * acc[mt][nt][0]);
                    atomicAdd(out + (size_t)t0 * H_DIM + c0 + 1, w0 * acc[mt][nt][1]);
                }
                if (t1 >= 0) {
                    atomicAdd(out + (size_t)t1 * H_DIM + c0,     w1 * acc[mt][nt][2]);
                    atomicAdd(out + (size_t)t1 * H_DIM + c0 + 1, w1 * acc[mt][nt][3]);
                }
            }
        }
    }
}

// ---------------- launch ----------------
extern "C" void kernel_launch(void* const* d_in, const int* in_sizes, int n_in,
                              void* d_out, int out_size) {
    const float* X   = (const float*)d_in[0];
    const float* rw  = (const float*)d_in[1];
    const int*   sel = (const int*)  d_in[2];
    const float* W1  = (const float*)d_in[3];
    const float* W2  = (const float*)d_in[4];
    float* out = (float*)d_out;

    constexpr int SMEM = 2 * STAGE_SZ;         // 106496
    static int cfg = 0;
    if (!cfg) {
        cudaFuncSetAttribute(k_gemm<1>, cudaFuncAttributeMaxDynamicSharedMemorySize, SMEM);
        cudaFuncSetAttribute(k_gemm<2>, cudaFuncAttributeMaxDynamicSharedMemorySize, SMEM);
        cfg = 1;
    }

    k_zero<<<256, 256>>>(out);
    k_route<<<1, 1024>>>(sel, rw);
    k_gather<<<MAXROWS, 256>>>(X);

    dim3 g1(MAXTILES, F_DIM / 64);   // 40 x 88, tile_m fast
    k_gemm<1><<<g1, 256, SMEM>>>(W1, nullptr);

    dim3 g2(MAXTILES, H_DIM / BM);   // 40 x 16
    k_gemm<2><<<g2, 256, SMEM>>>(W2, out);
}

// round 10
// speedup vs baseline: 1.5705x; 1.2217x over previous
#include <cuda_runtime.h>
#include <cuda_fp16.h>
#include <cstdint>

// ---------------- problem constants ----------------
#define T_TOK 2048
#define H_DIM 2048
#define F_DIM 5632
#define E_NUM 8
#define K_TOP 2
#define F2    (2 * F_DIM)

// ---------------- tiling ----------------
#define BM 128
#define BK 64
#define PITCH 72                    // A fp16 pitch in halves (144B)
#define PITCH32 72                  // B fp32 pitch in floats (288B, LDS.64 conflict-free)
#define A16_B (BM * PITCH * 2)      // 18432
#define B32_B (BM * PITCH32 * 4)    // 36864
#define STAGE_SZ (A16_B + B32_B)    // 55296
#define OFF_B32 A16_B
#define MAXROWS  5120
#define MAXTILES 40

// ---------------- device scratch ----------------
__device__ __half g_xg [(size_t)MAXROWS * H_DIM];
__device__ __half g_act[(size_t)MAXROWS * F_DIM];
__device__ int   g_tok[MAXROWS];
__device__ float g_wt [MAXROWS];
__device__ int   g_tile_expert[MAXTILES];

// ---------------- helpers ----------------
__device__ __forceinline__ uint32_t smem_u32(const void* p) {
    uint32_t a;
    asm("{ .reg .u64 t; cvta.to.shared.u64 t, %1; cvt.u32.u64 %0, t; }" : "=r"(a) : "l"(p));
    return a;
}
__device__ __forceinline__ void cpa16(uint32_t dst, const void* src) {
    asm volatile("cp.async.cg.shared.global [%0], [%1], 16;" :: "r"(dst), "l"(src));
}
#define CPA_COMMIT() asm volatile("cp.async.commit_group;" ::: "memory")
#define CPA_WAIT0()  asm volatile("cp.async.wait_group 0;" ::: "memory")

__device__ __forceinline__ void ldm4(uint32_t* r, uint32_t addr) {
    asm volatile("ldmatrix.sync.aligned.m8n8.x4.shared.b16 {%0,%1,%2,%3}, [%4];"
                 : "=r"(r[0]), "=r"(r[1]), "=r"(r[2]), "=r"(r[3]) : "r"(addr));
}
__device__ __forceinline__ void mma16816(float* d, const uint32_t* a, const uint32_t* b) {
    asm volatile(
        "mma.sync.aligned.m16n8k16.row.col.f32.f16.f16.f32 "
        "{%0,%1,%2,%3}, {%4,%5,%6,%7}, {%8,%9}, {%0,%1,%2,%3};\n"
        : "+f"(d[0]), "+f"(d[1]), "+f"(d[2]), "+f"(d[3])
        : "r"(a[0]), "r"(a[1]), "r"(a[2]), "r"(a[3]),
          "r"(b[0]), "r"(b[1]));
}
__device__ __forceinline__ uint32_t pack_h2(float a, float b) {
    __half2 h = __floats2half2_rn(a, b);
    return *(uint32_t*)&h;
}

// ---------------- routing ----------------
__global__ void k_zero(float* __restrict__ out) {
    int tid = blockIdx.x * blockDim.x + threadIdx.x;
    int nt  = gridDim.x * blockDim.x;
    for (int i = tid; i < T_TOK * H_DIM; i += nt) out[i] = 0.0f;
}
__global__ void k_route(const int* __restrict__ sel, const float* __restrict__ rw) {
    __shared__ int cnt[E_NUM];
    __shared__ int cur[E_NUM];
    const int tid = threadIdx.x;
    if (tid < E_NUM) cnt[tid] = 0;
    for (int i = tid; i < MAXROWS; i += blockDim.x) { g_tok[i] = -1; g_wt[i] = 0.0f; }
    __syncthreads();
    for (int i = tid; i < T_TOK * K_TOP; i += blockDim.x) atomicAdd(&cnt[sel[i]], 1);
    __syncthreads();
    if (tid == 0) {
        for (int t = 0; t < MAXTILES; ++t) g_tile_expert[t] = -1;
        int off = 0;
        for (int e = 0; e < E_NUM; ++e) {
            cur[e] = off;
            int tiles = (cnt[e] + BM - 1) / BM;
            for (int j = 0; j < tiles; ++j) g_tile_expert[off / BM + j] = e;
            off += tiles * BM;
        }
    }
    __syncthreads();
    for (int i = tid; i < T_TOK * K_TOP; i += blockDim.x) {
        int e = sel[i];
        int pos = atomicAdd(&cur[e], 1);
        g_tok[pos] = i / K_TOP;
        g_wt[pos]  = rw[i];
    }
}
__global__ void k_gather(const float* __restrict__ X) {
    const int row = blockIdx.x;
    if (g_tile_expert[row >> 7] < 0) return;
    const int tok = g_tok[row];
    uint2* dst = (uint2*)(g_xg + (size_t)row * H_DIM);
    if (tok >= 0) {
        const float4* src = (const float4*)(X + (size_t)tok * H_DIM);
        for (int i = threadIdx.x; i < H_DIM / 4; i += blockDim.x) {
            float4 v = src[i];
            dst[i] = make_uint2(pack_h2(v.x, v.y), pack_h2(v.z, v.w));
        }
    } else {
        for (int i = threadIdx.x; i < H_DIM / 4; i += blockDim.x)
            dst[i] = make_uint2(0u, 0u);
    }
}

// ---------------- fp16 tensor GEMM: 4 warps x (64x64) warp tiles ----------------
// grid: x = tile_m (fast -> L2 reuse of B), y = tile_n
// MODE 1: A = g_xg [128 x H] fp16, B = 64 gate ‖ 64 up fp32 rows of W1[e] -> silu -> g_act
// MODE 2: A = g_act [128 x F] fp16, B = 128 fp32 rows of W2[e] -> weighted atomicAdd -> out
template <int MODE>
__global__ void __launch_bounds__(128, 2)
k_gemm(const float* __restrict__ W, float* __restrict__ out) {
    constexpr int KD = (MODE == 1) ? H_DIM : F_DIM;
    constexpr int NC = KD / BK;               // 32 or 88

    const int tile_m = blockIdx.x;
    const int tile_n = blockIdx.y;
    const int e = g_tile_expert[tile_m];
    if (e < 0) return;

    extern __shared__ char smem[];
    const uint32_t sb = smem_u32(smem);

    const int tid  = threadIdx.x;
    const int lane = tid & 31;
    const int warp = tid >> 5;
    const int wm   = warp & 1;                 // 2 warps along M (64 rows each)
    const int wn   = warp >> 1;                // 2 warps along N (64 cols each)

    // A cp.async: 1024 granules, 8/thread; row = j*16 + (tid>>3), q = tid&7
    const __half* Aptr = (((MODE == 1) ? g_xg : g_act) + (size_t)tile_m * BM * KD)
                         + (size_t)(tid >> 3) * KD + (tid & 7) * 8;
    const uint32_t doffA = (uint32_t)((tid >> 3) * (PITCH * 2) + (tid & 7) * 16);

    // B fp32 cp.async: 2048 granules, 16/thread; row = j*8 + (tid>>4), q = tid&15
    const int brow = tid >> 4;                 // 0..7
    const int bq   = tid & 15;
    const float* ptrG;
    const float* ptrU = nullptr;
    if (MODE == 1) {
        const float* Bg = W + (size_t)e * F2 * H_DIM + (size_t)tile_n * 64 * H_DIM;
        ptrG = Bg + (size_t)brow * KD + bq * 4;
        ptrU = Bg + (size_t)F_DIM * H_DIM + (size_t)brow * KD + bq * 4;
    } else {
        ptrG = (W + (size_t)e * H_DIM * F_DIM + (size_t)tile_n * BM * F_DIM)
               + (size_t)brow * KD + bq * 4;
    }
    const uint32_t doffB = (uint32_t)(brow * (PITCH32 * 4) + bq * 16);

    float acc[4][8][4];
#pragma unroll
    for (int mt = 0; mt < 4; ++mt)
#pragma unroll
        for (int nt = 0; nt < 8; ++nt)
#pragma unroll
            for (int r = 0; r < 4; ++r) acc[mt][nt][r] = 0.0f;

    // A ldmatrix lane base
    const uint32_t lmoff = (uint32_t)((wm * 64 + (lane & 7) + ((lane >> 3) & 1) * 8) * (PITCH * 2)
                                      + (lane >> 4) * 16);
    // B fp32 fragment base: row n = wn*64 + nt*8 + (lane>>2), float pair at (lane&3)*2
    const uint32_t lboff = (uint32_t)((wn * 64 + (lane >> 2)) * (PITCH32 * 4) + (lane & 3) * 8);

    auto issue = [&](int c, int s) {
        const uint32_t base = sb + s * STAGE_SZ;
        const int koff = c * BK;
#pragma unroll
        for (int j = 0; j < 8; ++j)
            cpa16(base + doffA + j * 16 * (PITCH * 2), Aptr + (size_t)j * 16 * KD + koff);
#pragma unroll
        for (int j = 0; j < 16; ++j) {
            const float* src = (MODE == 1)
                ? ((j < 8) ? ptrG + (size_t)j * 8 * KD : ptrU + (size_t)(j - 8) * 8 * KD)
                : ptrG + (size_t)j * 8 * KD;
            cpa16(base + OFF_B32 + doffB + j * 8 * (PITCH32 * 4), src + koff);
        }
        CPA_COMMIT();
    };

    issue(0, 0);

#pragma unroll 1
    for (int c = 0; c < NC; ++c) {
        const int s = c & 1;
        CPA_WAIT0();
        __syncthreads();
        if (c + 1 < NC) issue(c + 1, s ^ 1);

        const uint32_t As = sb + s * STAGE_SZ;
        const char* Bs = smem + s * STAGE_SZ + OFF_B32;
#pragma unroll
        for (int ks = 0; ks < 4; ++ks) {
            uint32_t a[4][4];
#pragma unroll
            for (int mt = 0; mt < 4; ++mt)
                ldm4(a[mt], As + lmoff + mt * 16 * (PITCH * 2) + ks * 32);
            uint32_t b[8][2];
#pragma unroll
            for (int nt = 0; nt < 8; ++nt) {
                const char* bp = Bs + lboff + nt * 8 * (PITCH32 * 4) + ks * 64;
                float2 v0 = *(const float2*)bp;
                float2 v1 = *(const float2*)(bp + 32);
                b[nt][0] = pack_h2(v0.x, v0.y);
                b[nt][1] = pack_h2(v1.x, v1.y);
            }
#pragma unroll
            for (int mt = 0; mt < 4; ++mt)
#pragma unroll
                for (int nt = 0; nt < 8; ++nt)
                    mma16816(acc[mt][nt], a[mt], b[nt]);
        }
    }

    // ---------------- epilogue ----------------
    if (MODE == 1) {
        // wn==0 warps hold gate (cols 0-63), wn==1 warps hold up (cols 64-127)
        constexpr int XP = 65;
        float* xg = (float*)smem;              // 128 x 65 fp32 = 33.3 KB
        __syncthreads();
        if (wn == 0) {
#pragma unroll
            for (int mt = 0; mt < 4; ++mt) {
                const int r0 = wm * 64 + mt * 16 + (lane >> 2);
#pragma unroll
                for (int nt = 0; nt < 8; ++nt) {
                    const int c0 = nt * 8 + (lane & 3) * 2;
                    xg[r0 * XP + c0]           = acc[mt][nt][0];
                    xg[r0 * XP + c0 + 1]       = acc[mt][nt][1];
                    xg[(r0 + 8) * XP + c0]     = acc[mt][nt][2];
                    xg[(r0 + 8) * XP + c0 + 1] = acc[mt][nt][3];
                }
            }
        }
        __syncthreads();
        if (wn == 1) {
#pragma unroll
            for (int mt = 0; mt < 4; ++mt) {
                const int rl = wm * 64 + mt * 16 + (lane >> 2);
                const int grow0 = tile_m * BM + rl;
#pragma unroll
                for (int nt = 0; nt < 8; ++nt) {
                    const int c0 = nt * 8 + (lane & 3) * 2;
                    float g0 = xg[rl * XP + c0];
                    float g1 = xg[rl * XP + c0 + 1];
                    float g2 = xg[(rl + 8) * XP + c0];
                    float g3 = xg[(rl + 8) * XP + c0 + 1];
                    float o0 = acc[mt][nt][0] * g0 / (1.0f + expf(-g0));
                    float o1 = acc[mt][nt][1] * g1 / (1.0f + expf(-g1));
                    float o2 = acc[mt][nt][2] * g2 / (1.0f + expf(-g2));
                    float o3 = acc[mt][nt][3] * g3 / (1.0f + expf(-g3));
                    *(uint32_t*)(g_act + (size_t)grow0 * F_DIM + tile_n * 64 + c0)       = pack_h2(o0, o1);
                    *(uint32_t*)(g_act + (size_t)(grow0 + 8) * F_DIM + tile_n * 64 + c0) = pack_h2(o2, o3);
                }
            }
        }
    } else {
#pragma unroll
        for (int mt = 0; mt < 4; ++mt) {
            const int r0 = tile_m * BM + wm * 64 + mt * 16 + (lane >> 2);
            const int t0 = g_tok[r0];
            const int t1 = g_tok[r0 + 8];
            const float w0 = g_wt[r0];
            const float w1 = g_wt[r0 + 8];
#pragma unroll
            for (int nt = 0; nt < 8; ++nt) {
                const int c0 = tile_n * BM + wn * 64 + nt * 8 + (lane & 3) * 2;
                if (t0 >= 0) {
                    atomicAdd(out + (size_t)t0 * H_DIM + c0,     w0 * acc[mt][nt][0]);
                    atomicAdd(out + (size_t)t0 * H_DIM + c0 + 1, w0 * acc[mt][nt][1]);
                }
                if (t1 >= 0) {
                    atomicAdd(out + (size_t)t1 * H_DIM + c0,     w1 * acc[mt][nt][2]);
                    atomicAdd(out + (size_t)t1 * H_DIM + c0 + 1, w1 * acc[mt][nt][3]);
                }
            }
        }
    }
}

// ---------------- launch ----------------
extern "C" void kernel_launch(void* const* d_in, const int* in_sizes, int n_in,
                              void* d_out, int out_size) {
    const float* X   = (const float*)d_in[0];
    const float* rw  = (const float*)d_in[1];
    const int*   sel = (const int*)  d_in[2];
    const float* W1  = (const float*)d_in[3];
    const float* W2  = (const float*)d_in[4];
    float* out = (float*)d_out;

    constexpr int SMEM = 2 * STAGE_SZ;         // 110592
    static int cfg = 0;
    if (!cfg) {
        cudaFuncSetAttribute(k_gemm<1>, cudaFuncAttributeMaxDynamicSharedMemorySize, SMEM);
        cudaFuncSetAttribute(k_gemm<2>, cudaFuncAttributeMaxDynamicSharedMemorySize, SMEM);
        cfg = 1;
    }

    k_zero<<<256, 256>>>(out);
    k_route<<<1, 1024>>>(sel, rw);
    k_gather<<<MAXROWS, 256>>>(X);

    dim3 g1(MAXTILES, F_DIM / 64);   // 40 x 88, tile_m fast
    k_gemm<1><<<g1, 128, SMEM>>>(W1, nullptr);

    dim3 g2(MAXTILES, H_DIM / BM);   // 40 x 16
    k_gemm<2><<<g2, 128, SMEM>>>(W2, out);
}